// round 1
// baseline (speedup 1.0000x reference)
#include <cuda_runtime.h>
#include <cstdint>

#define BSZ 16
#define TQ 1024
#define TMK 1024
#define DMODEL 512
#define NHEAD 8
#define DH 64
#define QT 32
#define KT 64
#define KPAD 68
#define NEGV (-4294967295.0f)

// ---------------- scratch (device globals: no allocation allowed) ----------------
__device__ float g_Q[(size_t)BSZ * TQ * DMODEL];
__device__ float g_K[(size_t)BSZ * TMK * DMODEL];
__device__ float g_V[(size_t)BSZ * TMK * DMODEL];

// ---------------- fast exp: FMA-pipe only (no MUFU, no F2I) ----------------
// valid for x <= 0 (post max-subtraction). exp(x) = 2^(x*log2e).
__device__ __forceinline__ float fast_exp_neg(float x) {
    float t = x * 1.4426950408889634f;
    t = fmaxf(t, -125.0f);                 // clamp huge-negative (masked) values
    float z = t + 12582912.0f;             // round-to-nearest-int via magic number
    float fi = z - 12582912.0f;            // = round(t)
    float f = t - fi;                      // in [-0.5, 0.5]
    int   i = __float_as_int(z) - 0x4B400000;  // integer part
    // 2^f Taylor deg-5 (max rel err ~2.4e-6 on [-0.5,0.5])
    float r = 1.3333558146e-3f;
    r = fmaf(r, f, 9.6181291076e-3f);
    r = fmaf(r, f, 5.5504108664e-2f);
    r = fmaf(r, f, 2.4022650696e-1f);
    r = fmaf(r, f, 6.9314718056e-1f);
    r = fmaf(r, f, 1.0f);
    return __int_as_float(__float_as_int(r) + (i << 23));   // * 2^i
}

// ---------------- kernel 1: QKV projections (128x128x16 SGEMM, 8x8/thread) ----------------
__global__ __launch_bounds__(256) void proj_kernel(
    const float* __restrict__ inputs, const float* __restrict__ memory,
    const float* __restrict__ Wq, const float* __restrict__ Wk, const float* __restrict__ Wv)
{
    const int sel = blockIdx.z;
    const float* A = (sel == 0) ? inputs : memory;
    const float* W = (sel == 0) ? Wq : (sel == 1 ? Wk : Wv);
    float* out = (sel == 0) ? g_Q : (sel == 1 ? g_K : g_V);

    __shared__ float As[16][130];   // transposed, padded (conflict-free)
    __shared__ float Bs[16][128];

    const int row0 = blockIdx.y * 128;
    const int col0 = blockIdx.x * 128;
    const int tid = threadIdx.x;
    const int tx = tid & 15;
    const int ty = tid >> 4;

    float acc[8][8];
    #pragma unroll
    for (int i = 0; i < 8; i++)
        #pragma unroll
        for (int j = 0; j < 8; j++) acc[i][j] = 0.f;

    for (int k0 = 0; k0 < DMODEL; k0 += 16) {
        #pragma unroll
        for (int i = 0; i < 2; i++) {
            int u = tid + i * 256;              // 0..511 float4 units
            int r = u >> 2;
            int c4 = (u & 3) * 4;
            float4 v = *(const float4*)(A + (size_t)(row0 + r) * DMODEL + k0 + c4);
            As[c4 + 0][r] = v.x; As[c4 + 1][r] = v.y;
            As[c4 + 2][r] = v.z; As[c4 + 3][r] = v.w;
        }
        #pragma unroll
        for (int i = 0; i < 2; i++) {
            int u = tid + i * 256;
            int r = u >> 5;
            int c4 = (u & 31) * 4;
            *(float4*)&Bs[r][c4] = *(const float4*)(W + (size_t)(k0 + r) * DMODEL + col0 + c4);
        }
        __syncthreads();
        #pragma unroll
        for (int kk = 0; kk < 16; kk++) {
            float a[8], bb[8];
            #pragma unroll
            for (int i = 0; i < 8; i++) a[i] = As[kk][ty + 16 * i];
            #pragma unroll
            for (int j = 0; j < 8; j++) bb[j] = Bs[kk][tx + 16 * j];
            #pragma unroll
            for (int i = 0; i < 8; i++)
                #pragma unroll
                for (int j = 0; j < 8; j++) acc[i][j] = fmaf(a[i], bb[j], acc[i][j]);
        }
        __syncthreads();
    }
    #pragma unroll
    for (int i = 0; i < 8; i++)
        #pragma unroll
        for (int j = 0; j < 8; j++)
            out[(size_t)(row0 + ty + 16 * i) * DMODEL + col0 + tx + 16 * j] = acc[i][j];
}

// ---------------- kernel 2: fused attention ----------------
// One CTA = (b, h, 32 q-rows). Whole softmax row (1024 k) lives in SMEM.
// smem: Ls[32][1024] (128KB) + Qs[32][64] (8KB) + KVs[64][68] (17KB) = 156672 B
#define ATTN_SMEM ((QT * TMK + QT * DH + KT * KPAD) * 4)

__global__ __launch_bounds__(256) void attn_kernel(
    const int* __restrict__ mem_len, const int* __restrict__ qry_len,
    const int* __restrict__ caus_p,
    float* __restrict__ ctx, float* __restrict__ aln)
{
    extern __shared__ float sm[];
    float* Ls  = sm;                    // [32][1024]
    float* Qs  = sm + QT * TMK;         // [32][64]
    float* KVs = Qs + QT * DH;          // [64][68]

    const int qt = blockIdx.x;          // 0..31
    const int h  = blockIdx.y;
    const int b  = blockIdx.z;
    const int q0 = qt * QT;
    const int tid  = threadIdx.x;
    const int lane = tid & 31;
    const int w    = tid >> 5;          // warp 0..7

    const int mlen = mem_len[b];
    const int qlen = qry_len[b];
    const int caus = caus_p ? caus_p[0] : 1;
    const int qmax = q0 + QT - 1;

    // load Q tile (pre-scaled by 1/sqrt(dh)/temperature = 1/8)
    {
        const float scale = 0.125f;
        const float* Qg = g_Q + (size_t)(b * TQ + q0) * DMODEL + h * DH;
        #pragma unroll
        for (int i = 0; i < 2; i++) {
            int u = tid + i * 256;          // 0..511 float4 units
            int r = u >> 4;
            int d4 = (u & 15) * 4;
            float4 v = *(const float4*)(Qg + (size_t)r * DMODEL + d4);
            v.x *= scale; v.y *= scale; v.z *= scale; v.w *= scale;
            *(float4*)&Qs[r * DH + d4] = v;
        }
    }
    __syncthreads();

    // ---- stage 1: masked logits into Ls ----
    for (int kt = 0; kt < TMK / KT; kt++) {
        const int k0 = kt * KT;
        const bool dead = (caus && k0 > qmax) || (k0 >= mlen);
        if (dead) {   // entire 32x64 tile masked -> fill NEG, skip GEMM
            #pragma unroll
            for (int i = 0; i < 8; i++) {
                int u = tid + i * 256;
                Ls[(u >> 6) * TMK + k0 + (u & 63)] = NEGV;
            }
            continue;
        }
        __syncthreads();   // previous tile's KVs consumers done
        #pragma unroll
        for (int i = 0; i < 4; i++) {
            int u = tid + i * 256;          // 0..1023 float4 units
            int kk = u >> 4;
            int d4 = (u & 15) * 4;
            *(float4*)&KVs[kk * KPAD + d4] =
                *(const float4*)(g_K + (size_t)(b * TMK + k0 + kk) * DMODEL + h * DH + d4);
        }
        __syncthreads();
        // warp w -> rows w*4..+3, lane -> cols 2*lane, 2*lane+1
        float acc[4][2] = {};
        #pragma unroll
        for (int d4 = 0; d4 < DH; d4 += 4) {
            float4 q4[4], k4[2];
            #pragma unroll
            for (int i = 0; i < 4; i++) q4[i] = *(float4*)&Qs[(w * 4 + i) * DH + d4];
            #pragma unroll
            for (int j = 0; j < 2; j++) k4[j] = *(float4*)&KVs[(lane * 2 + j) * KPAD + d4];
            #pragma unroll
            for (int i = 0; i < 4; i++)
                #pragma unroll
                for (int j = 0; j < 2; j++) {
                    acc[i][j] = fmaf(q4[i].x, k4[j].x, acc[i][j]);
                    acc[i][j] = fmaf(q4[i].y, k4[j].y, acc[i][j]);
                    acc[i][j] = fmaf(q4[i].z, k4[j].z, acc[i][j]);
                    acc[i][j] = fmaf(q4[i].w, k4[j].w, acc[i][j]);
                }
        }
        #pragma unroll
        for (int i = 0; i < 4; i++) {
            const int q = q0 + w * 4 + i;
            #pragma unroll
            for (int j = 0; j < 2; j++) {
                const int k = k0 + lane * 2 + j;
                const bool valid = (k < mlen) && (q < qlen) && (!caus || k <= q);
                Ls[(w * 4 + i) * TMK + k] = valid ? acc[i][j] : NEGV;
            }
        }
    }
    __syncthreads();

    // ---- stage 2: row softmax in SMEM + coalesced alignment store ----
    #pragma unroll 1
    for (int i = 0; i < 4; i++) {
        const int r = w * 4 + i;
        float4* Lr = (float4*)&Ls[r * TMK];
        float4 buf[8];
        float vmax = -3.4e38f;
        #pragma unroll
        for (int m = 0; m < 8; m++) {
            buf[m] = Lr[lane + 32 * m];
            vmax = fmaxf(vmax, fmaxf(fmaxf(buf[m].x, buf[m].y), fmaxf(buf[m].z, buf[m].w)));
        }
        #pragma unroll
        for (int s = 16; s > 0; s >>= 1) vmax = fmaxf(vmax, __shfl_xor_sync(0xffffffffu, vmax, s));
        float ssum = 0.f;
        #pragma unroll
        for (int m = 0; m < 8; m++) {
            buf[m].x = fast_exp_neg(buf[m].x - vmax);
            buf[m].y = fast_exp_neg(buf[m].y - vmax);
            buf[m].z = fast_exp_neg(buf[m].z - vmax);
            buf[m].w = fast_exp_neg(buf[m].w - vmax);
            ssum += (buf[m].x + buf[m].y) + (buf[m].z + buf[m].w);
        }
        #pragma unroll
        for (int s = 16; s > 0; s >>= 1) ssum += __shfl_xor_sync(0xffffffffu, ssum, s);
        const float rinv = 1.0f / ssum;
        float4* Ag = aln ? (float4*)(aln + ((size_t)(b * NHEAD + h) * TQ + q0 + r) * TMK) : nullptr;
        #pragma unroll
        for (int m = 0; m < 8; m++) {
            float4 p;
            p.x = buf[m].x * rinv; p.y = buf[m].y * rinv;
            p.z = buf[m].z * rinv; p.w = buf[m].w * rinv;
            Lr[lane + 32 * m] = p;
            if (Ag) Ag[lane + 32 * m] = p;
        }
    }
    __syncthreads();

    // ---- stage 3: PV (contexts) ----
    float c_[4][2] = {};
    const bool allvalid = (qmax < qlen);   // no fully-masked (uniform) rows in tile
    for (int kt = 0; kt < TMK / KT; kt++) {
        const int k0 = kt * KT;
        if (allvalid && ((caus && k0 > qmax) || (k0 >= mlen))) continue;  // p ~ 0 here
        __syncthreads();
        #pragma unroll
        for (int i = 0; i < 4; i++) {
            int u = tid + i * 256;
            int kk = u >> 4;
            int d4 = (u & 15) * 4;
            *(float4*)&KVs[kk * KPAD + d4] =
                *(const float4*)(g_V + (size_t)(b * TMK + k0 + kk) * DMODEL + h * DH + d4);
        }
        __syncthreads();
        #pragma unroll 4
        for (int kk4 = 0; kk4 < KT; kk4 += 4) {
            float4 p4[4];
            #pragma unroll
            for (int i = 0; i < 4; i++) p4[i] = *(float4*)&Ls[(w * 4 + i) * TMK + k0 + kk4];
            #pragma unroll
            for (int u = 0; u < 4; u++) {
                float2 v2 = *(float2*)&KVs[(kk4 + u) * KPAD + lane * 2];
                #pragma unroll
                for (int i = 0; i < 4; i++) {
                    float p = (u == 0) ? p4[i].x : (u == 1) ? p4[i].y : (u == 2) ? p4[i].z : p4[i].w;
                    c_[i][0] = fmaf(p, v2.x, c_[i][0]);
                    c_[i][1] = fmaf(p, v2.y, c_[i][1]);
                }
            }
        }
    }
    if (ctx) {
        #pragma unroll
        for (int i = 0; i < 4; i++) {
            const int q = q0 + w * 4 + i;
            float2* cg = (float2*)(ctx + (size_t)(b * TQ + q) * DMODEL + h * DH);
            cg[lane] = make_float2(c_[i][0], c_[i][1]);
        }
    }
}

// ---------------- launch ----------------
extern "C" void kernel_launch(void* const* d_in, const int* in_sizes, int n_in,
                              void* d_out, int out_size) {
    const float* inputs = (const float*)d_in[0];
    const float* memory = (const float*)d_in[1];
    const float* Wq     = (const float*)d_in[2];
    const float* Wk     = (const float*)d_in[3];
    const float* Wv     = (const float*)d_in[4];
    const int* mlen     = (const int*)d_in[5];
    const int* qlen     = (const int*)d_in[6];
    const int* caus     = (n_in > 7) ? (const int*)d_in[7] : nullptr;

    float* out = (float*)d_out;
    const long long ctx_elems = (long long)BSZ * TQ * DMODEL;         // 8388608
    const long long aln_elems = (long long)BSZ * NHEAD * TQ * TMK;    // 134217728
    float* ctx = nullptr;
    float* aln = nullptr;
    if ((long long)out_size >= ctx_elems + aln_elems) { ctx = out; aln = out + ctx_elems; }
    else if ((long long)out_size >= aln_elems)        { aln = out; }
    else                                              { ctx = out; }

    dim3 pg(DMODEL / 128, (BSZ * TQ) / 128, 3);
    proj_kernel<<<pg, 256>>>(inputs, memory, Wq, Wk, Wv);

    // idempotent; also succeeds on the pre-capture correctness call
    cudaFuncSetAttribute(attn_kernel, cudaFuncAttributeMaxDynamicSharedMemorySize, ATTN_SMEM);
    dim3 ag(TQ / QT, NHEAD, BSZ);
    attn_kernel<<<ag, 256, ATTN_SMEM>>>(mlen, qlen, caus, ctx, aln);
}

// round 5
// speedup vs baseline: 1.1571x; 1.1571x over previous
#include <cuda_runtime.h>
#include <cstdint>

#define BSZ 16
#define TQ 1024
#define TMK 1024
#define DMODEL 512
#define NHEAD 8
#define DH 64
#define QT 32
#define KTT 256
#define KPAD 68
#define NEGV (-4294967295.0f)

// ---------------- scratch (device globals: no allocation allowed) ----------------
__device__ float g_Q[(size_t)BSZ * TQ * DMODEL];
__device__ float g_K[(size_t)BSZ * TMK * DMODEL];
__device__ float g_V[(size_t)BSZ * TMK * DMODEL];

// ---------------- fast exp: FMA-pipe only (no MUFU, no F2I) ----------------
// valid for x <= 0 (post max-subtraction). exp(x) = 2^(x*log2e).
__device__ __forceinline__ float fast_exp_neg(float x) {
    float t = x * 1.4426950408889634f;
    t = fmaxf(t, -125.0f);                 // clamp huge-negative (masked) values
    float z = t + 12582912.0f;             // round-to-nearest-int via magic number
    float fi = z - 12582912.0f;            // = round(t)
    float f = t - fi;                      // in [-0.5, 0.5]
    int   i = __float_as_int(z) - 0x4B400000;  // integer part
    float r = 1.3333558146e-3f;
    r = fmaf(r, f, 9.6181291076e-3f);
    r = fmaf(r, f, 5.5504108664e-2f);
    r = fmaf(r, f, 2.4022650696e-1f);
    r = fmaf(r, f, 6.9314718056e-1f);
    r = fmaf(r, f, 1.0f);
    return __int_as_float(__float_as_int(r) + (i << 23));   // * 2^i
}

// ---------------- kernel 1: QKV projections (v3: register-prefetch double buffer) ----------------
__global__ __launch_bounds__(256) void proj_kernel(
    const float* __restrict__ inputs, const float* __restrict__ memory,
    const float* __restrict__ Wq, const float* __restrict__ Wk, const float* __restrict__ Wv)
{
    const int sel = blockIdx.z;
    const float* A = (sel == 0) ? inputs : memory;
    const float* W = (sel == 0) ? Wq : (sel == 1 ? Wk : Wv);
    float* out = (sel == 0) ? g_Q : (sel == 1 ? g_K : g_V);

    __shared__ float As[16][130];   // transposed, padded (conflict-free)
    __shared__ float Bs[16][128];

    const int row0 = blockIdx.y * 128;
    const int col0 = blockIdx.x * 128;
    const int tid = threadIdx.x;
    const int tx = tid & 15;
    const int ty = tid >> 4;

    // per-thread load coordinates (fixed across k-steps)
    const int ar0 = (tid + 0)   >> 2, ac0 = ((tid + 0)   & 3) * 4;
    const int ar1 = (tid + 256) >> 2, ac1 = ((tid + 256) & 3) * 4;
    const int br0 = (tid + 0)   >> 5, bc0 = ((tid + 0)   & 31) * 4;
    const int br1 = (tid + 256) >> 5, bc1 = ((tid + 256) & 31) * 4;

    float acc[8][8];
    #pragma unroll
    for (int i = 0; i < 8; i++)
        #pragma unroll
        for (int j = 0; j < 8; j++) acc[i][j] = 0.f;

    // prefetch k-step 0 into registers
    float4 pa0 = *(const float4*)(A + (size_t)(row0 + ar0) * DMODEL + ac0);
    float4 pa1 = *(const float4*)(A + (size_t)(row0 + ar1) * DMODEL + ac1);
    float4 pb0 = *(const float4*)(W + (size_t)br0 * DMODEL + col0 + bc0);
    float4 pb1 = *(const float4*)(W + (size_t)br1 * DMODEL + col0 + bc1);

    for (int k0 = 0; k0 < DMODEL; k0 += 16) {
        // commit prefetched fragments to smem
        As[ac0 + 0][ar0] = pa0.x; As[ac0 + 1][ar0] = pa0.y;
        As[ac0 + 2][ar0] = pa0.z; As[ac0 + 3][ar0] = pa0.w;
        As[ac1 + 0][ar1] = pa1.x; As[ac1 + 1][ar1] = pa1.y;
        As[ac1 + 2][ar1] = pa1.z; As[ac1 + 3][ar1] = pa1.w;
        *(float4*)&Bs[br0][bc0] = pb0;
        *(float4*)&Bs[br1][bc1] = pb1;
        __syncthreads();

        // issue next k-step's global loads (latency overlapped with compute below)
        if (k0 + 16 < DMODEL) {
            const int kn = k0 + 16;
            pa0 = *(const float4*)(A + (size_t)(row0 + ar0) * DMODEL + kn + ac0);
            pa1 = *(const float4*)(A + (size_t)(row0 + ar1) * DMODEL + kn + ac1);
            pb0 = *(const float4*)(W + (size_t)(kn + br0) * DMODEL + col0 + bc0);
            pb1 = *(const float4*)(W + (size_t)(kn + br1) * DMODEL + col0 + bc1);
        }

        #pragma unroll
        for (int kk = 0; kk < 16; kk++) {
            float a[8], bb[8];
            #pragma unroll
            for (int i = 0; i < 8; i++) a[i] = As[kk][ty + 16 * i];
            #pragma unroll
            for (int j = 0; j < 8; j++) bb[j] = Bs[kk][tx + 16 * j];
            #pragma unroll
            for (int i = 0; i < 8; i++)
                #pragma unroll
                for (int j = 0; j < 8; j++) acc[i][j] = fmaf(a[i], bb[j], acc[i][j]);
        }
        __syncthreads();
    }
    #pragma unroll
    for (int i = 0; i < 8; i++)
        #pragma unroll
        for (int j = 0; j < 8; j++)
            out[(size_t)(row0 + ty + 16 * i) * DMODEL + col0 + tx + 16 * j] = acc[i][j];
}

// ---------------- kernel 2: fused attention (v2: 512 thr, conflict-free, split-K PV) ----------------
// smem: Ls[32][1024] (128KB) + Qs[32][64] (8KB, aliased as Ps in stage 3) + KVs[256][68] (68KB)
#define ATTN_SMEM ((QT * TMK + QT * DH + KTT * KPAD) * 4)

__global__ __launch_bounds__(512) void attn_kernel(
    const int* __restrict__ mem_len, const int* __restrict__ qry_len,
    const int* __restrict__ caus_p,
    float* __restrict__ ctx, float* __restrict__ aln)
{
    extern __shared__ float sm[];
    float* Ls  = sm;                    // [32][1024]
    float* Qs  = sm + QT * TMK;         // [32][64]
    float* KVs = Qs + QT * DH;          // [256][68]

    const int qt = blockIdx.x;          // 0..31
    const int h  = blockIdx.y;
    const int b  = blockIdx.z;
    const int q0 = qt * QT;
    const int tid  = threadIdx.x;
    const int lane = tid & 31;
    const int w    = tid >> 5;          // warp 0..15
    const int rg   = w & 7;             // row group: rows rg*4..rg*4+3
    const int cg   = w >> 3;            // col half:  0 or 1

    const int mlen = mem_len[b];
    const int qlen = qry_len[b];
    const int caus = caus_p ? caus_p[0] : 1;
    const int qmax = q0 + QT - 1;

    // load Q tile (pre-scaled by 1/sqrt(dh)/temperature = 1/8)
    {
        const float scale = 0.125f;
        const float* Qg = g_Q + (size_t)(b * TQ + q0) * DMODEL + h * DH;
        int r = tid >> 4;
        int d4 = (tid & 15) * 4;
        float4 v = *(const float4*)(Qg + (size_t)r * DMODEL + d4);
        v.x *= scale; v.y *= scale; v.z *= scale; v.w *= scale;
        *(float4*)&Qs[r * DH + d4] = v;
    }
    __syncthreads();

    // ---- stage 1: masked logits into Ls ----
    for (int kt = 0; kt < TMK / KTT; kt++) {
        const int k0 = kt * KTT;
        const bool deadt = (caus && k0 > qmax) || (k0 >= mlen);
        if (deadt) {   // entire 32x256 tile masked -> fill NEG, skip
            #pragma unroll
            for (int i = 0; i < 4; i++) {
                int u = tid + i * 512;          // 0..2047 float4 units
                int r = u >> 6;
                int c4 = (u & 63) * 4;
                *(float4*)&Ls[r * TMK + k0 + c4] = make_float4(NEGV, NEGV, NEGV, NEGV);
            }
            continue;
        }
        __syncthreads();   // previous tile's KVs consumers done
        #pragma unroll
        for (int i = 0; i < 8; i++) {
            int u = tid + i * 512;          // 0..4095 float4 units
            int kk = u >> 4;
            int d4 = (u & 15) * 4;
            *(float4*)&KVs[kk * KPAD + d4] =
                *(const float4*)(g_K + (size_t)(b * TMK + k0 + kk) * DMODEL + h * DH + d4);
        }
        __syncthreads();

        const int kw0 = k0 + cg * 128;      // this warp's 128-col sub-range
        const bool wdead = (caus && kw0 > qmax) || (kw0 >= mlen);
        if (wdead) {   // warp's sub-range fully masked
            #pragma unroll
            for (int i = 0; i < 4; i++)
                #pragma unroll
                for (int j = 0; j < 4; j++)
                    Ls[(rg * 4 + i) * TMK + kw0 + lane + 32 * j] = NEGV;
            continue;
        }
        // thread tile 4 rows x 4 cols; cols = kw0 + lane + 32*j (conflict-free: KPAD%32==4)
        float acc[4][4] = {};
        const float* Qr = &Qs[(rg * 4) * DH];
        const float* Kr = &KVs[(cg * 128 + lane) * KPAD];
        #pragma unroll
        for (int d4 = 0; d4 < DH; d4 += 4) {
            float4 q4[4], k4[4];
            #pragma unroll
            for (int i = 0; i < 4; i++) q4[i] = *(const float4*)&Qr[i * DH + d4];
            #pragma unroll
            for (int j = 0; j < 4; j++) k4[j] = *(const float4*)&Kr[(32 * j) * KPAD + d4];
            #pragma unroll
            for (int i = 0; i < 4; i++)
                #pragma unroll
                for (int j = 0; j < 4; j++) {
                    acc[i][j] = fmaf(q4[i].x, k4[j].x, acc[i][j]);
                    acc[i][j] = fmaf(q4[i].y, k4[j].y, acc[i][j]);
                    acc[i][j] = fmaf(q4[i].z, k4[j].z, acc[i][j]);
                    acc[i][j] = fmaf(q4[i].w, k4[j].w, acc[i][j]);
                }
        }
        #pragma unroll
        for (int i = 0; i < 4; i++) {
            const int q = q0 + rg * 4 + i;
            #pragma unroll
            for (int j = 0; j < 4; j++) {
                const int k = kw0 + lane + 32 * j;
                const bool valid = (k < mlen) && (q < qlen) && (!caus || k <= q);
                Ls[(rg * 4 + i) * TMK + k] = valid ? acc[i][j] : NEGV;
            }
        }
    }
    __syncthreads();

    // ---- stage 2: row softmax in SMEM + coalesced alignment store (2 rows/warp) ----
    #pragma unroll 1
    for (int i = 0; i < 2; i++) {
        const int r = w * 2 + i;
        float4* Lr = (float4*)&Ls[r * TMK];
        float4 buf[8];
        float vmax = -3.4e38f;
        #pragma unroll
        for (int m = 0; m < 8; m++) {
            buf[m] = Lr[lane + 32 * m];
            vmax = fmaxf(vmax, fmaxf(fmaxf(buf[m].x, buf[m].y), fmaxf(buf[m].z, buf[m].w)));
        }
        #pragma unroll
        for (int s = 16; s > 0; s >>= 1) vmax = fmaxf(vmax, __shfl_xor_sync(0xffffffffu, vmax, s));
        float ssum = 0.f;
        #pragma unroll
        for (int m = 0; m < 8; m++) {
            buf[m].x = fast_exp_neg(buf[m].x - vmax);
            buf[m].y = fast_exp_neg(buf[m].y - vmax);
            buf[m].z = fast_exp_neg(buf[m].z - vmax);
            buf[m].w = fast_exp_neg(buf[m].w - vmax);
            ssum += (buf[m].x + buf[m].y) + (buf[m].z + buf[m].w);
        }
        #pragma unroll
        for (int s = 16; s > 0; s >>= 1) ssum += __shfl_xor_sync(0xffffffffu, ssum, s);
        const float rinv = 1.0f / ssum;
        float4* Ag = aln ? (float4*)(aln + ((size_t)(b * NHEAD + h) * TQ + q0 + r) * TMK) : nullptr;
        #pragma unroll
        for (int m = 0; m < 8; m++) {
            float4 p;
            p.x = buf[m].x * rinv; p.y = buf[m].y * rinv;
            p.z = buf[m].z * rinv; p.w = buf[m].w * rinv;
            Lr[lane + 32 * m] = p;
            if (Ag) Ag[lane + 32 * m] = p;
        }
    }
    __syncthreads();

    // ---- stage 3: PV (contexts), split-K across the two warp groups ----
    float c0_[4] = {}, c1_[4] = {};          // rows rg*4+i, dims lane*2, lane*2+1
    const bool allvalid = (qmax < qlen);     // no fully-masked (uniform) rows in tile
    for (int kt = 0; kt < TMK / KTT; kt++) {
        const int k0 = kt * KTT;
        if (allvalid && ((caus && k0 > qmax) || (k0 >= mlen))) continue;  // p ~ 0 here
        __syncthreads();
        #pragma unroll
        for (int i = 0; i < 8; i++) {
            int u = tid + i * 512;
            int kk = u >> 4;
            int d4 = (u & 15) * 4;
            *(float4*)&KVs[kk * KPAD + d4] =
                *(const float4*)(g_V + (size_t)(b * TMK + k0 + kk) * DMODEL + h * DH + d4);
        }
        __syncthreads();
        const int kbase = cg * 128;          // group's 128-row k sub-range
        const bool sub_dead = allvalid && ((caus && (k0 + kbase) > qmax) || (k0 + kbase >= mlen));
        if (sub_dead) continue;
        #pragma unroll 4
        for (int kk = 0; kk < 128; kk += 4) {
            float4 p4[4];
            #pragma unroll
            for (int i = 0; i < 4; i++)
                p4[i] = *(const float4*)&Ls[(rg * 4 + i) * TMK + k0 + kbase + kk];
            #pragma unroll
            for (int u = 0; u < 4; u++) {
                float2 v2 = *(const float2*)&KVs[(kbase + kk + u) * KPAD + lane * 2];
                #pragma unroll
                for (int i = 0; i < 4; i++) {
                    float p = (u == 0) ? p4[i].x : (u == 1) ? p4[i].y : (u == 2) ? p4[i].z : p4[i].w;
                    c0_[i] = fmaf(p, v2.x, c0_[i]);
                    c1_[i] = fmaf(p, v2.y, c1_[i]);
                }
            }
        }
    }
    // combine the two groups' partial sums via Ps (aliases Qs)
    __syncthreads();
    float* Ps = Qs;
    if (cg == 0) {
        #pragma unroll
        for (int i = 0; i < 4; i++)
            *(float2*)&Ps[(rg * 4 + i) * DH + lane * 2] = make_float2(c0_[i], c1_[i]);
    }
    __syncthreads();
    if (cg == 1 && ctx) {
        #pragma unroll
        for (int i = 0; i < 4; i++) {
            const int q = q0 + rg * 4 + i;
            float2 pp = *(const float2*)&Ps[(rg * 4 + i) * DH + lane * 2];
            float2 v = make_float2(c0_[i] + pp.x, c1_[i] + pp.y);
            *(float2*)(ctx + (size_t)(b * TQ + q) * DMODEL + h * DH + lane * 2) = v;
        }
    }
}

// ---------------- launch ----------------
extern "C" void kernel_launch(void* const* d_in, const int* in_sizes, int n_in,
                              void* d_out, int out_size) {
    const float* inputs = (const float*)d_in[0];
    const float* memory = (const float*)d_in[1];
    const float* Wq     = (const float*)d_in[2];
    const float* Wk     = (const float*)d_in[3];
    const float* Wv     = (const float*)d_in[4];
    const int* mlen     = (const int*)d_in[5];
    const int* qlen     = (const int*)d_in[6];
    const int* caus     = (n_in > 7) ? (const int*)d_in[7] : nullptr;

    float* out = (float*)d_out;
    const long long ctx_elems = (long long)BSZ * TQ * DMODEL;         // 8388608
    const long long aln_elems = (long long)BSZ * NHEAD * TQ * TMK;    // 134217728
    float* ctx = nullptr;
    float* aln = nullptr;
    if ((long long)out_size >= ctx_elems + aln_elems) { ctx = out; aln = out + ctx_elems; }
    else if ((long long)out_size >= aln_elems)        { aln = out; }
    else                                              { ctx = out; }

    dim3 pg(DMODEL / 128, (BSZ * TQ) / 128, 3);
    proj_kernel<<<pg, 256>>>(inputs, memory, Wq, Wk, Wv);

    cudaFuncSetAttribute(attn_kernel, cudaFuncAttributeMaxDynamicSharedMemorySize, ATTN_SMEM);
    dim3 ag(TQ / QT, NHEAD, BSZ);
    attn_kernel<<<ag, 512, ATTN_SMEM>>>(mlen, qlen, caus, ctx, aln);
}